// round 2
// baseline (speedup 1.0000x reference)
#include <cuda_runtime.h>

// Problem constants (fixed shapes from the reference):
//   inputs: [B=4, C=8, H=256, W=256] f32  -> d_in[0], 2,097,152 elems
//   se_coef: scalar f32                    -> d_in[1], 1 elem
//   output: [B, C, S=4, H, W] f32          -> d_out, 8,388,608 elems
// Per scale k: t = 4^k, radius RAD = 4*2^k, penalty pen(x) = c * x^2 / (4t).
// Closing = Ev(Eh(Dv(Dh(x)))) per scale. Pads: -10000 (dilation) / +10000 (erosion),
// with the penalty applied to the pad value too (matches jnp.pad-then-subtract).

static constexpr int Wd = 256;
static constexpr int Hd = 256;
static constexpr int BCn = 32;   // B*C
static constexpr int Sn  = 4;

// Ping-pong scratch planes, [BC, S, H, W] layout (same as output layout).
__device__ float g_t1[(size_t)BCn * Sn * Hd * Wd];
__device__ float g_t2[(size_t)BCn * Sn * Hd * Wd];

// ---------------------------------------------------------------------------
// Horizontal pass. One CTA = 8 rows; one warp = one row; each thread computes
// 8 consecutive outputs. Padded row staged in smem, read back as float4.
// ISMAX=true: dilation, src = external input [BC,H,W], dst = g_t1.
// ISMAX=false: erosion, src = g_t2 [BC,S,H,W],       dst = g_t1.
// ---------------------------------------------------------------------------
template <int K, bool ISMAX>
__global__ void __launch_bounds__(256) hpass_kernel(const float* __restrict__ ext,
                                                    const float* __restrict__ cptr)
{
    constexpr int   RAD   = 4 << K;
    constexpr int   SP    = Wd + 2 * RAD;             // padded row pitch (mult of 4)
    constexpr float INV4T = 1.0f / (float)(1 << (2 * K + 2));
    constexpr float PADV  = ISMAX ? -10000.0f : 10000.0f;

    __shared__ float sbuf[8 * SP];

    const float c  = __ldg(cptr);
    const float pc = ISMAX ? -(c * INV4T) : (c * INV4T);

    const int row0 = blockIdx.x * 8;   // among BC*H = 8192 rows

    // ---- stage 8 padded rows into smem ----
    for (int i = threadIdx.x; i < 8 * SP; i += 256) {
        const int r  = i / SP;
        const int x  = i - r * SP;
        const int gr = row0 + r;
        const int bc = gr >> 8;
        const int h  = gr & 255;
        const int xin = x - RAD;
        float v = PADV;
        if ((unsigned)xin < (unsigned)Wd) {
            if constexpr (ISMAX) {
                v = ext[((size_t)bc * Hd + h) * Wd + xin];
            } else {
                v = g_t2[(((size_t)bc * Sn + K) * Hd + h) * Wd + xin];
            }
        }
        sbuf[i] = v;
    }
    __syncthreads();

    const int r = threadIdx.x >> 5;     // row within CTA (warp-per-row)
    const int q = threadIdx.x & 31;     // 8 outputs at x = 8q..8q+7
    const float* rb = &sbuf[r * SP + q * 8];

    float acc[8];
#pragma unroll
    for (int i = 0; i < 8; ++i) acc[i] = ISMAX ? -3.402823466e38f : 3.402823466e38f;

#pragma unroll
    for (int jc = 0; jc < (2 * RAD + 8) / 4; ++jc) {
        const float4 vv = *reinterpret_cast<const float4*>(rb + 4 * jc);
        const float va[4] = {vv.x, vv.y, vv.z, vv.w};
#pragma unroll
        for (int u = 0; u < 4; ++u) {
            const int jj = 4 * jc + u;
#pragma unroll
            for (int rr = 0; rr < 8; ++rr) {
                const int off = jj - rr - RAD;
                if (off >= -RAD && off <= RAD) {
                    const float t = fmaf(pc, (float)(off * off), va[u]);
                    acc[rr] = ISMAX ? fmaxf(acc[rr], t) : fminf(acc[rr], t);
                }
            }
        }
    }

    const int gr = row0 + r;
    const int bc = gr >> 8;
    const int h  = gr & 255;
    float* dp = g_t1 + (((size_t)bc * Sn + K) * Hd + h) * Wd + q * 8;
#pragma unroll
    for (int rr = 0; rr < 8; ++rr) dp[rr] = acc[rr];
}

// ---------------------------------------------------------------------------
// Vertical pass. One CTA = full 256-wide stripe x 8 output rows; thread = one
// column, streams the (2*RAD+8)-row window through registers with clamped LDG.
// ISMAX=true: dilation, src = g_t1, dst = g_t2.
// ISMAX=false: erosion, src = g_t1, dst = extdst (final output).
// ---------------------------------------------------------------------------
template <int K, bool ISMAX>
__global__ void __launch_bounds__(256) vpass_kernel(float* __restrict__ extdst,
                                                    const float* __restrict__ cptr)
{
    constexpr int   RAD   = 4 << K;
    constexpr float INV4T = 1.0f / (float)(1 << (2 * K + 2));
    constexpr float PADV  = ISMAX ? -10000.0f : 10000.0f;

    const float c  = __ldg(cptr);
    const float pc = ISMAX ? -(c * INV4T) : (c * INV4T);

    const int x  = threadIdx.x;
    const int r0 = blockIdx.x * 8;
    const int bc = blockIdx.y;

    const float* sp = g_t1 + (((size_t)bc * Sn + K) * Hd) * (size_t)Wd + x;

    float acc[8];
#pragma unroll
    for (int i = 0; i < 8; ++i) acc[i] = ISMAX ? -3.402823466e38f : 3.402823466e38f;

#pragma unroll
    for (int jj = 0; jj < 2 * RAD + 8; ++jj) {
        const int row = r0 + jj - RAD;
        float v = PADV;
        if ((unsigned)row < (unsigned)Hd) v = __ldg(sp + (size_t)row * Wd);
#pragma unroll
        for (int rr = 0; rr < 8; ++rr) {
            const int off = jj - rr - RAD;
            if (off >= -RAD && off <= RAD) {
                const float t = fmaf(pc, (float)(off * off), v);
                acc[rr] = ISMAX ? fmaxf(acc[rr], t) : fminf(acc[rr], t);
            }
        }
    }

    float* base;
    if constexpr (ISMAX) base = g_t2; else base = extdst;
    float* dp = base + (((size_t)bc * Sn + K) * Hd + r0) * Wd + x;
#pragma unroll
    for (int rr = 0; rr < 8; ++rr) dp[(size_t)rr * Wd] = acc[rr];
}

// ---------------------------------------------------------------------------
// Launch: 4 scales x (Dh, Dv, Eh, Ev). All graph-capturable, no allocations.
// ---------------------------------------------------------------------------
template <int K>
static void run_scale(const float* in, const float* cp, float* out)
{
    const dim3 hgrid(BCn * Hd / 8);        // 1024 CTAs
    const dim3 vgrid(Hd / 8, BCn);         // 32 x 32 CTAs
    hpass_kernel<K, true ><<<hgrid, 256>>>(in, cp);       // Dh: in   -> t1
    vpass_kernel<K, true ><<<vgrid, 256>>>(nullptr, cp);  // Dv: t1   -> t2
    hpass_kernel<K, false><<<hgrid, 256>>>(nullptr, cp);  // Eh: t2   -> t1
    vpass_kernel<K, false><<<vgrid, 256>>>(out, cp);      // Ev: t1   -> out
}

extern "C" void kernel_launch(void* const* d_in, const int* in_sizes, int n_in,
                              void* d_out, int out_size)
{
    const float* in = (const float*)d_in[0];
    const float* cp = (const float*)d_in[1];
    float* out = (float*)d_out;

    run_scale<0>(in, cp, out);
    run_scale<1>(in, cp, out);
    run_scale<2>(in, cp, out);
    run_scale<3>(in, cp, out);
}

// round 3
// speedup vs baseline: 1.4633x; 1.4633x over previous
#include <cuda_runtime.h>

// inputs: [B=4,C=8,H=256,W=256] f32 ; se_coef scalar f32 ; out [B,C,4,H,W] f32
// scale k: t=4^k, RAD=4*2^k, pen(j)=c*j^2/(4t). closing = Ev(Eh(Dv(Dh(x)))).
// pads: -10000 (dilation) / +10000 (erosion), penalty applied to pads too.

static constexpr int Wd = 256, Hd = 256, BCn = 32, Sn = 4;

__device__ float g_t1[(size_t)BCn * Sn * Hd * Wd];
__device__ float g_t2[(size_t)BCn * Sn * Hd * Wd];

template <bool ISMAX>
__device__ __forceinline__ float mm(float a, float b) {
    return ISMAX ? fmaxf(a, b) : fminf(a, b);
}

// ---------------------------------------------------------------------------
// Horizontal pass. CTA = 8 rows, warp = row, lane q -> outputs x=8q..8q+7.
// Padded row staged in smem transposed: s[x&7][x>>3] so every window read is
// (compile-time const) + q  -> conflict-free scalar LDS.
// Symmetric pairing: acc = mm(acc, fma(pc, j*j, mm(v[x-j], v[x+j]))).
// ---------------------------------------------------------------------------
template <int K, bool ISMAX>
__device__ __forceinline__ void hpass_impl(float* sb, const float* __restrict__ ext,
                                           const float* __restrict__ cptr)
{
    constexpr int   RAD   = 4 << K;
    constexpr int   SP    = Wd + 2 * RAD;
    constexpr int   PITCH = 41;                       // > (SP_max=320)/8
    constexpr float INV4T = 1.0f / (float)(1 << (2 * K + 2));
    constexpr float PADV  = ISMAX ? -10000.0f : 10000.0f;

    const float c  = __ldg(cptr);
    const float pc = (ISMAX ? -c : c) * INV4T;
    const int row0 = blockIdx.x * 8;                  // among BC*H = 8192 rows

    for (int i = threadIdx.x; i < 8 * SP; i += 256) {
        const int r = i / SP, x = i - r * SP;
        const int gr = row0 + r, bc = gr >> 8, h = gr & 255;
        const int xin = x - RAD;
        float v = PADV;
        if ((unsigned)xin < (unsigned)Wd) {
            v = ISMAX ? ext[((size_t)bc * Hd + h) * Wd + xin]
                      : g_t2[(((size_t)bc * Sn + K) * Hd + h) * Wd + xin];
        }
        sb[(r * 8 + (x & 7)) * PITCH + (x >> 3)] = v;
    }
    __syncthreads();

    const int r = threadIdx.x >> 5, q = threadIdx.x & 31;
    const float* rowb = sb + r * 8 * PITCH + q;
    // x = 8q + C  ->  word index ((C&7)*PITCH + (C>>3)) + q   (C compile-time)
#define HLD(C) rowb[(((C) & 7) * PITCH) + ((C) >> 3)]

    float val[2 * RAD + 8], acc[8];
#pragma unroll
    for (int rr = 0; rr < 8; ++rr) {
        val[RAD + rr] = HLD(RAD + rr);
        acc[rr] = val[RAD + rr];                       // j=0 term, pen=0
    }
#pragma unroll
    for (int j = 1; j <= RAD; ++j) {
        val[RAD - j]     = HLD(RAD - j);
        val[RAD + 7 + j] = HLD(RAD + 7 + j);
#pragma unroll
        for (int rr = 0; rr < 8; ++rr) {
            const float m = mm<ISMAX>(val[RAD + rr - j], val[RAD + rr + j]);
            acc[rr] = mm<ISMAX>(acc[rr], fmaf(pc, (float)(j * j), m));
        }
    }
#undef HLD

    const int gr = row0 + r, bc = gr >> 8, h = gr & 255;
    float* dp = g_t1 + (((size_t)bc * Sn + K) * Hd + h) * Wd + q * 8;
    reinterpret_cast<float4*>(dp)[0] = make_float4(acc[0], acc[1], acc[2], acc[3]);
    reinterpret_cast<float4*>(dp)[1] = make_float4(acc[4], acc[5], acc[6], acc[7]);
}

template <bool ISMAX>
__global__ void __launch_bounds__(256) hpass_all(const float* __restrict__ ext,
                                                 const float* __restrict__ cptr)
{
    __shared__ float sb[8 * 8 * 41];                  // 10.25 KB, shared by all K
    switch (blockIdx.y) {
        case 0:  hpass_impl<0, ISMAX>(sb, ext, cptr); break;
        case 1:  hpass_impl<1, ISMAX>(sb, ext, cptr); break;
        case 2:  hpass_impl<2, ISMAX>(sb, ext, cptr); break;
        default: hpass_impl<3, ISMAX>(sb, ext, cptr); break;
    }
}

// ---------------------------------------------------------------------------
// Vertical pass. Thread = 2 adjacent cols (float2) x 8 consecutive out rows.
// CTA = 128 thr = 256 cols. Interior CTAs take an unpredicated path.
// ---------------------------------------------------------------------------
template <int K, bool ISMAX, bool SAFE>
__device__ __forceinline__ void vbody(const float* __restrict__ sp,
                                      float* __restrict__ dst,
                                      const float pc, const int r0)
{
    constexpr int   RAD  = 4 << K;
    constexpr float PADV = ISMAX ? -10000.0f : 10000.0f;

    float2 val[2 * RAD + 8], acc[8];

#define VLD(d)                                                                  \
    [&]() -> float2 {                                                           \
        const int row_ = r0 + (d) - RAD;                                        \
        if constexpr (SAFE) {                                                   \
            return *reinterpret_cast<const float2*>(sp + (size_t)row_ * Wd);    \
        } else {                                                                \
            if ((unsigned)row_ < (unsigned)Hd)                                  \
                return *reinterpret_cast<const float2*>(sp + (size_t)row_ * Wd);\
            return make_float2(PADV, PADV);                                     \
        }                                                                       \
    }()

#pragma unroll
    for (int rr = 0; rr < 8; ++rr) {
        val[RAD + rr] = VLD(RAD + rr);
        acc[rr] = val[RAD + rr];
    }
#pragma unroll
    for (int j = 1; j <= RAD; ++j) {
        val[RAD - j]     = VLD(RAD - j);
        val[RAD + 7 + j] = VLD(RAD + 7 + j);
        const float pj = fmaf(pc, (float)(j * j), 0.0f);  // pc*j^2 (j^2 imm)
#pragma unroll
        for (int rr = 0; rr < 8; ++rr) {
            const float2 a = val[RAD + rr - j], b = val[RAD + rr + j];
            acc[rr].x = mm<ISMAX>(acc[rr].x, mm<ISMAX>(a.x, b.x) + pj);
            acc[rr].y = mm<ISMAX>(acc[rr].y, mm<ISMAX>(a.y, b.y) + pj);
        }
    }
#undef VLD

#pragma unroll
    for (int rr = 0; rr < 8; ++rr)
        *reinterpret_cast<float2*>(dst + (size_t)rr * Wd) = acc[rr];
}

template <int K, bool ISMAX>
__device__ __forceinline__ void vpass_impl(float* __restrict__ extdst,
                                           const float* __restrict__ cptr)
{
    constexpr int   RAD   = 4 << K;
    constexpr float INV4T = 1.0f / (float)(1 << (2 * K + 2));
    const float c  = __ldg(cptr);
    const float pc = (ISMAX ? -c : c) * INV4T;

    const int x  = (int)threadIdx.x * 2;
    const int r0 = blockIdx.x * 8;
    const int bc = blockIdx.y;

    const float* sp = g_t1 + ((size_t)(bc * Sn + K) * Hd) * Wd + x;
    float* base = ISMAX ? g_t2 : extdst;
    float* dst  = base + (((size_t)bc * Sn + K) * Hd + r0) * Wd + x;

    if (r0 >= RAD && r0 + 7 + RAD < Hd) vbody<K, ISMAX, true >(sp, dst, pc, r0);
    else                                vbody<K, ISMAX, false>(sp, dst, pc, r0);
}

template <bool ISMAX>
__global__ void __launch_bounds__(128) vpass_all(float* __restrict__ extdst,
                                                 const float* __restrict__ cptr)
{
    switch (blockIdx.z) {
        case 0:  vpass_impl<0, ISMAX>(extdst, cptr); break;
        case 1:  vpass_impl<1, ISMAX>(extdst, cptr); break;
        case 2:  vpass_impl<2, ISMAX>(extdst, cptr); break;
        default: vpass_impl<3, ISMAX>(extdst, cptr); break;
    }
}

// ---------------------------------------------------------------------------
// 4 launches total: Dh(all K) -> Dv(all K) -> Eh(all K) -> Ev(all K).
// Graph-capturable: kernel launches only, no allocations.
// ---------------------------------------------------------------------------
extern "C" void kernel_launch(void* const* d_in, const int* in_sizes, int n_in,
                              void* d_out, int out_size)
{
    const float* in = (const float*)d_in[0];
    const float* cp = (const float*)d_in[1];
    float* out = (float*)d_out;

    const dim3 hgrid(BCn * Hd / 8, Sn);        // 1024 x 4
    const dim3 vgrid(Hd / 8, BCn, Sn);         // 32 x 32 x 4

    hpass_all<true ><<<hgrid, 256>>>(in, cp);       // Dh: in -> t1
    vpass_all<true ><<<vgrid, 128>>>(nullptr, cp);  // Dv: t1 -> t2
    hpass_all<false><<<hgrid, 256>>>(nullptr, cp);  // Eh: t2 -> t1
    vpass_all<false><<<vgrid, 128>>>(out, cp);      // Ev: t1 -> out
}

// round 5
// speedup vs baseline: 1.5284x; 1.0445x over previous
#include <cuda_runtime.h>

// inputs: [B=4,C=8,H=256,W=256] f32 ; se_coef scalar f32 ; out [B,C,4,H,W] f32
// scale k: t=4^k, RAD=4*2^k, pen(j)=c*j^2/(4t). closing = Ev(Eh(Dv(Dh(x)))).
// pads: -10000 (dilation) / +10000 (erosion), penalty applied to pads too.

static constexpr int Wd = 256, Hd = 256, BCn = 32, Sn = 4;

// Vertically padded scratch planes: per (bc,k) plane has RAD_k pad rows on
// top & bottom. t2 shares the layout (its pads are never read).
__host__ __device__ constexpr int plsz(int k) { return (Hd + 2 * (4 << k)) * Wd; }
__host__ __device__ constexpr int plo(int k) {
    return (k == 0) ? 0
         : (k == 1) ? plsz(0)
         : (k == 2) ? plsz(0) + plsz(1)
                    : plsz(0) + plsz(1) + plsz(2);
}
static constexpr int BCS = plsz(0) + plsz(1) + plsz(2) + plsz(3);  // 292864

__device__ float g_t1[(size_t)BCn * BCS];
__device__ float g_t2[(size_t)BCn * BCS];

template <bool ISMAX>
__device__ __forceinline__ float mm(float a, float b) {
    return ISMAX ? fmaxf(a, b) : fminf(a, b);
}

// ---------------------------------------------------------------------------
// Pad fill: CTA (k, bc) writes PADV into the 2*RAD pad rows of its t1 plane.
// ---------------------------------------------------------------------------
__global__ void __launch_bounds__(256) padfill_kernel(float v)
{
    const int k  = blockIdx.x;
    const int bc = blockIdx.y;
    const int RAD = 4 << k;
    float* plane = g_t1 + (size_t)bc * BCS + plo(k);
    const int band = RAD * Wd;                 // top band elems
    for (int i = threadIdx.x; i < 2 * band; i += 256) {
        const int idx = (i < band) ? i : i + Hd * Wd;
        plane[idx] = v;
    }
}

// ---------------------------------------------------------------------------
// Horizontal pass. CTA = 8 rows, warp = row, lane q -> outputs x=8q..8q+7.
// Padded row staged transposed in smem (conflict-free reads). Sliding 8-wide
// register queues L/R; symmetric pairing.
// DIL (ISMAX=true): src = ext input [BC,H,W].  ERO: src = g_t2 interior.
// dst = g_t1 interior rows.
// ---------------------------------------------------------------------------
template <int K, bool ISMAX>
__device__ __forceinline__ void hpass_impl(float* sb, const float* __restrict__ ext,
                                           const float* __restrict__ cptr)
{
    constexpr int   RAD   = 4 << K;
    constexpr int   SP    = Wd + 2 * RAD;
    constexpr int   PITCH = 41;
    constexpr float INV4T = 1.0f / (float)(1 << (2 * K + 2));
    constexpr float PADV  = ISMAX ? -10000.0f : 10000.0f;

    const float c  = __ldg(cptr);
    const float pc = (ISMAX ? -c : c) * INV4T;
    const int row0 = blockIdx.y * 8;                  // among BC*H = 8192 rows

    for (int i = threadIdx.x; i < 8 * SP; i += 256) {
        const int r = i / SP, x = i - r * SP;
        const int gr = row0 + r, bc = gr >> 8, h = gr & 255;
        const int xin = x - RAD;
        float v = PADV;
        if ((unsigned)xin < (unsigned)Wd) {
            v = ISMAX ? ext[((size_t)bc * Hd + h) * Wd + xin]
                      : g_t2[(size_t)bc * BCS + plo(K) + (RAD + h) * Wd + xin];
        }
        sb[(r * 8 + (x & 7)) * PITCH + (x >> 3)] = v;
    }
    __syncthreads();

    const int r = threadIdx.x >> 5, q = threadIdx.x & 31;
    const float* rowb = sb + r * 8 * PITCH + q;
#define HLD(C) rowb[(((C) & 7) * PITCH) + ((C) >> 3)]

    float acc[8], L[8], R[8];
#pragma unroll
    for (int rr = 0; rr < 8; ++rr) {
        acc[rr] = HLD(RAD + rr);
        L[rr] = acc[rr];
        R[rr] = acc[rr];
    }
#pragma unroll
    for (int j = 1; j <= RAD; ++j) {
#pragma unroll
        for (int i = 7; i > 0; --i) L[i] = L[i - 1];
        L[0] = HLD(RAD - j);
#pragma unroll
        for (int i = 0; i < 7; ++i) R[i] = R[i + 1];
        R[7] = HLD(RAD + 7 + j);
#pragma unroll
        for (int rr = 0; rr < 8; ++rr)
            acc[rr] = mm<ISMAX>(acc[rr],
                                fmaf(pc, (float)(j * j), mm<ISMAX>(L[rr], R[rr])));
    }
#undef HLD

    const int gr = row0 + r, bc = gr >> 8, h = gr & 255;
    float* dp = g_t1 + (size_t)bc * BCS + plo(K) + (RAD + h) * Wd + q * 8;
    reinterpret_cast<float4*>(dp)[0] = make_float4(acc[0], acc[1], acc[2], acc[3]);
    reinterpret_cast<float4*>(dp)[1] = make_float4(acc[4], acc[5], acc[6], acc[7]);
}

template <bool ISMAX>
__global__ void __launch_bounds__(256, 5) hpass_all(const float* __restrict__ ext,
                                                    const float* __restrict__ cptr)
{
    __shared__ float sb[8 * 8 * 41];
    switch (blockIdx.x) {
        case 0:  hpass_impl<0, ISMAX>(sb, ext, cptr); break;
        case 1:  hpass_impl<1, ISMAX>(sb, ext, cptr); break;
        case 2:  hpass_impl<2, ISMAX>(sb, ext, cptr); break;
        default: hpass_impl<3, ISMAX>(sb, ext, cptr); break;
    }
}

// ---------------------------------------------------------------------------
// Vertical pass. CTA = 256 threads = 256 cols; thread computes 16 output rows.
// Src rows come from the padded t1 plane -> NO bounds checks anywhere.
// Sliding 16-wide register queues T/B.
// DIL: dst = t2 interior (padded layout). ERO: dst = final output.
// ---------------------------------------------------------------------------
template <int K, bool ISMAX>
__device__ __forceinline__ void vpass_impl(float* __restrict__ extdst,
                                           const float* __restrict__ cptr)
{
    constexpr int   RAD   = 4 << K;
    constexpr float INV4T = 1.0f / (float)(1 << (2 * K + 2));
    const float c  = __ldg(cptr);
    const float pc = (ISMAX ? -c : c) * INV4T;

    const int x  = threadIdx.x;
    const int r0 = blockIdx.y * 16;                  // output row block
    const int bc = blockIdx.z;

    // padded plane: output row r reads padded rows (RAD + r) +- j
    const float* sp = g_t1 + (size_t)bc * BCS + plo(K) + (size_t)r0 * Wd + x;
#define VLD(D) sp[(size_t)(D) * Wd]

    float acc[16], T[16], B[16];
#pragma unroll
    for (int rr = 0; rr < 16; ++rr) {
        acc[rr] = VLD(RAD + rr);
        T[rr] = acc[rr];
        B[rr] = acc[rr];
    }
#pragma unroll
    for (int j = 1; j <= RAD; ++j) {
#pragma unroll
        for (int i = 15; i > 0; --i) T[i] = T[i - 1];
        T[0] = VLD(RAD - j);
#pragma unroll
        for (int i = 0; i < 15; ++i) B[i] = B[i + 1];
        B[15] = VLD(RAD + 15 + j);
#pragma unroll
        for (int rr = 0; rr < 16; ++rr)
            acc[rr] = mm<ISMAX>(acc[rr],
                                fmaf(pc, (float)(j * j), mm<ISMAX>(T[rr], B[rr])));
    }
#undef VLD

    if constexpr (ISMAX) {
        float* dp = g_t2 + (size_t)bc * BCS + plo(K) + (size_t)(RAD + r0) * Wd + x;
#pragma unroll
        for (int rr = 0; rr < 16; ++rr) dp[(size_t)rr * Wd] = acc[rr];
    } else {
        float* dp = extdst + (((size_t)bc * Sn + K) * Hd + r0) * Wd + x;
#pragma unroll
        for (int rr = 0; rr < 16; ++rr) dp[(size_t)rr * Wd] = acc[rr];
    }
}

template <bool ISMAX>
__global__ void __launch_bounds__(256, 4) vpass_all(float* __restrict__ extdst,
                                                    const float* __restrict__ cptr)
{
    switch (blockIdx.x) {
        case 0:  vpass_impl<0, ISMAX>(extdst, cptr); break;
        case 1:  vpass_impl<1, ISMAX>(extdst, cptr); break;
        case 2:  vpass_impl<2, ISMAX>(extdst, cptr); break;
        default: vpass_impl<3, ISMAX>(extdst, cptr); break;
    }
}

// ---------------------------------------------------------------------------
// 6 launches: pad(t1,-) ; Dh ; Dv ; pad(t1,+) ; Eh ; Ev.  Graph-capturable.
// ---------------------------------------------------------------------------
extern "C" void kernel_launch(void* const* d_in, const int* in_sizes, int n_in,
                              void* d_out, int out_size)
{
    const float* in = (const float*)d_in[0];
    const float* cp = (const float*)d_in[1];
    float* out = (float*)d_out;

    const dim3 pgrid(Sn, BCn);                 // 4 x 32
    const dim3 hgrid(Sn, BCn * Hd / 8);        // 4 x 1024
    const dim3 vgrid(Sn, Hd / 16, BCn);        // 4 x 16 x 32

    padfill_kernel<<<pgrid, 256>>>(-10000.0f);
    hpass_all<true ><<<hgrid, 256>>>(in, cp);       // Dh: in -> t1
    vpass_all<true ><<<vgrid, 256>>>(nullptr, cp);  // Dv: t1 -> t2
    padfill_kernel<<<pgrid, 256>>>(10000.0f);
    hpass_all<false><<<hgrid, 256>>>(nullptr, cp);  // Eh: t2 -> t1
    vpass_all<false><<<vgrid, 256>>>(out, cp);      // Ev: t1 -> out
}